// round 9
// baseline (speedup 1.0000x reference)
#include <cuda_runtime.h>
#include <cuda_fp16.h>
#include <cstdint>

#define B_ 4
#define C_ 64
#define N_ 4096
#define NT2 32              // 4096 / 128-key tiles
#define LOG2E 1.4426950408889634f
#define ONES16 0x3C003C00u
#define MLAG 3.5f           // lagging-max rescale threshold (log2 units)

// Fragment-ordered scratch. uint4 units.
// g_qf: [b][rowblk N/16][hl][cstep 4][lane 32]            (A-frag, LOG2E-folded)
// g_kf: [b][jblk N/64][hl][cstep 4][jpair 4][lane 32]     (B-frag pairs)
// g_vf: [b][jblk][kstep 4][cpair 4][lane 32]              (hi only)
__device__ uint4 g_qf[4 * 256 * 2 * 4 * 32];
__device__ uint4 g_kf[4 * 64 * 2 * 4 * 4 * 32];
__device__ uint4 g_vf[4 * 64 * 4 * 4 * 32];

// ---------------------------------------------------------------------------
__device__ __forceinline__ void cp16(uint32_t d, const void* g) {
    asm volatile("cp.async.cg.shared.global [%0], [%1], 16;"
                 :: "r"(d), "l"(__cvta_generic_to_global(g)) : "memory");
}
__device__ __forceinline__ uint4 lds128(uint32_t a) {
    uint4 r;
    asm volatile("ld.shared.v4.u32 {%0,%1,%2,%3}, [%4];"
                 : "=r"(r.x), "=r"(r.y), "=r"(r.z), "=r"(r.w) : "r"(a));
    return r;
}
__device__ __forceinline__ void mma16816(float* d, const uint32_t* a,
                                         uint32_t b0, uint32_t b1) {
    asm volatile("mma.sync.aligned.m16n8k16.row.col.f32.f16.f16.f32 "
        "{%0,%1,%2,%3}, {%4,%5,%6,%7}, {%8,%9}, {%0,%1,%2,%3};"
        : "+f"(d[0]), "+f"(d[1]), "+f"(d[2]), "+f"(d[3])
        : "r"(a[0]), "r"(a[1]), "r"(a[2]), "r"(a[3]), "r"(b0), "r"(b1));
}
__device__ __forceinline__ uint32_t cvtpk(float hi, float lo) {
    uint32_t r;
    asm("cvt.rn.f16x2.f32 %0, %1, %2;" : "=r"(r) : "f"(hi), "f"(lo));
    return r;
}
__device__ __forceinline__ uint32_t ex2x2(uint32_t a) {
    uint32_t r;
    asm("ex2.approx.f16x2 %0, %1;" : "=r"(r) : "r"(a));
    return r;
}
__device__ __forceinline__ float ex2f(float x) {
    float r;
    asm("ex2.approx.f32 %0, %1;" : "=f"(r) : "f"(x));
    return r;
}
__device__ __forceinline__ uint32_t pkh(float x0, float x1) {
    __half h0 = __float2half_rn(x0), h1 = __float2half_rn(x1);
    return ((uint32_t)__half_as_ushort(h1) << 16) | __half_as_ushort(h0);
}

// 128-key tile: K(hi+lo) 32KB + V(hi) 16KB. 128 threads.
__device__ __forceinline__ void copy_tile(uint32_t sdst, int b, int t2, int tid) {
    const uint4* gk = g_kf + ((size_t)b * 64 + t2 * 2) * 1024;
    const uint4* gv = g_vf + ((size_t)b * 64 + t2 * 2) * 512;
    #pragma unroll
    for (int k = 0; k < 16; k++) {
        int i = tid + k * 128;
        cp16(sdst + i * 16, gk + i);
    }
    #pragma unroll
    for (int k = 0; k < 8; k++) {
        int i = tid + k * 128;
        cp16(sdst + 32768 + i * 16, gv + i);
    }
}

// ---------------------------------------------------------------------------
// per-stream pieces (macros over register arrays to keep everything inlined)
// ---------------------------------------------------------------------------
struct Stream {
    float s[8][4];
    float o[9][4];   // 8 out blocks + rowsum (ones column)
    float mu0, mu1;  // lagging max actually used as subtractor
};

__device__ __forceinline__ void qk_half(Stream& st, uint32_t sK, uint32_t half16k,
                                        const uint32_t (*qh)[4],
                                        const uint32_t (*ql)[4],
                                        uint32_t lanoff) {
    #pragma unroll
    for (int nb = 0; nb < 8; nb++)
        #pragma unroll
        for (int i = 0; i < 4; i++) st.s[nb][i] = 0.f;
    #pragma unroll
    for (int cs = 0; cs < 4; cs++) {
        #pragma unroll
        for (int jp = 0; jp < 4; jp++) {
            uint32_t base = sK + half16k + (cs * 4 + jp) * 512 + lanoff;
            uint4 KH = lds128(base);
            uint4 KL = lds128(base + 8192);
            mma16816(st.s[2*jp],   qh[cs], KH.x, KH.y);
            mma16816(st.s[2*jp],   ql[cs], KH.x, KH.y);
            mma16816(st.s[2*jp],   qh[cs], KL.x, KL.y);
            mma16816(st.s[2*jp+1], qh[cs], KH.z, KH.w);
            mma16816(st.s[2*jp+1], ql[cs], KH.z, KH.w);
            mma16816(st.s[2*jp+1], qh[cs], KL.z, KL.w);
        }
    }
}

__device__ __forceinline__ void softmax_pv(Stream& st, uint32_t sV,
                                           uint32_t vhalf8k, uint32_t lanoff) {
    // row max of this tile-half
    float t0 = fmaxf(fmaxf(st.s[0][0], st.s[0][1]), fmaxf(st.s[1][0], st.s[1][1]));
    float t1 = fmaxf(fmaxf(st.s[0][2], st.s[0][3]), fmaxf(st.s[1][2], st.s[1][3]));
    #pragma unroll
    for (int nb = 2; nb < 8; nb++) {
        t0 = fmaxf(t0, fmaxf(st.s[nb][0], st.s[nb][1]));
        t1 = fmaxf(t1, fmaxf(st.s[nb][2], st.s[nb][3]));
    }
    t0 = fmaxf(t0, __shfl_xor_sync(0xffffffffu, t0, 1));
    t0 = fmaxf(t0, __shfl_xor_sync(0xffffffffu, t0, 2));
    t1 = fmaxf(t1, __shfl_xor_sync(0xffffffffu, t1, 1));
    t1 = fmaxf(t1, __shfl_xor_sync(0xffffffffu, t1, 2));

    // lagging-max: rescale only when the subtractor must move
    bool need = (t0 > st.mu0 + MLAG) || (t1 > st.mu1 + MLAG);
    if (__ballot_sync(0xffffffffu, need)) {
        const float m0n = fmaxf(st.mu0, t0), m1n = fmaxf(st.mu1, t1);
        const float a0 = ex2f(st.mu0 - m0n), a1 = ex2f(st.mu1 - m1n);
        #pragma unroll
        for (int nb = 0; nb < 9; nb++) {
            st.o[nb][0] *= a0; st.o[nb][1] *= a0;
            st.o[nb][2] *= a1; st.o[nb][3] *= a1;
        }
        st.mu0 = m0n; st.mu1 = m1n;
    }

    uint32_t p[8][2];
    #pragma unroll
    for (int nb = 0; nb < 8; nb++) {
        p[nb][0] = ex2x2(cvtpk(st.s[nb][1] - st.mu0, st.s[nb][0] - st.mu0));
        p[nb][1] = ex2x2(cvtpk(st.s[nb][3] - st.mu1, st.s[nb][2] - st.mu1));
    }

    #pragma unroll
    for (int s4 = 0; s4 < 4; s4++) {
        uint32_t a[4] = { p[2*s4][0], p[2*s4][1], p[2*s4+1][0], p[2*s4+1][1] };
        #pragma unroll
        for (int cp = 0; cp < 4; cp++) {
            uint4 VH = lds128(sV + vhalf8k + (s4 * 4 + cp) * 512 + lanoff);
            mma16816(st.o[2*cp],   a, VH.x, VH.y);
            mma16816(st.o[2*cp+1], a, VH.z, VH.w);
        }
        mma16816(st.o[8], a, ONES16, ONES16);
    }
}

// ---------------------------------------------------------------------------
// Flash attention: 64 q-rows/CTA (4 warps x 16 rows), 128-key tiles.
// TWO independent key-streams per warp (keys 0-63 / 64-127 of each tile):
// softmax of stream A retires under stream B's queued MMAs and vice versa.
// ---------------------------------------------------------------------------
__global__ void __launch_bounds__(128, 2) attn_tc(float* __restrict__ out)
{
    extern __shared__ uint8_t smraw[];
    const uint32_t smbase = (uint32_t)__cvta_generic_to_shared(smraw);
    const int tid = threadIdx.x, w = tid >> 5, lane = tid & 31;
    const int g = lane >> 2, tq = lane & 3;
    const int b = blockIdx.x >> 6, qblk = blockIdx.x & 63;

    // persistent Q fragments (hi/lo), 32 regs
    uint32_t qh[4][4], ql[4][4];
    {
        const uint4* qp = g_qf + ((size_t)(b * 256 + qblk * 4 + w)) * 256 + lane;
        #pragma unroll
        for (int cs = 0; cs < 4; cs++) {
            uint4 h = qp[cs * 32];
            qh[cs][0] = h.x; qh[cs][1] = h.y; qh[cs][2] = h.z; qh[cs][3] = h.w;
            uint4 l = qp[128 + cs * 32];
            ql[cs][0] = l.x; ql[cs][1] = l.y; ql[cs][2] = l.z; ql[cs][3] = l.w;
        }
    }

    Stream A, Bs;
    #pragma unroll
    for (int nb = 0; nb < 9; nb++)
        #pragma unroll
        for (int i = 0; i < 4; i++) { A.o[nb][i] = 0.f; Bs.o[nb][i] = 0.f; }
    A.mu0 = -1e30f; A.mu1 = -1e30f; Bs.mu0 = -1e30f; Bs.mu1 = -1e30f;

    const uint32_t lanoff = (uint32_t)(lane * 16);

    copy_tile(smbase, b, 0, tid);
    asm volatile("cp.async.commit_group;" ::: "memory");

    for (int t = 0; t < NT2; t++) {
        if (t + 1 < NT2) {
            copy_tile(smbase + ((t + 1) & 1) * 49152, b, t + 1, tid);
            asm volatile("cp.async.commit_group;" ::: "memory");
            asm volatile("cp.async.wait_group 1;" ::: "memory");
        } else {
            asm volatile("cp.async.wait_group 0;" ::: "memory");
        }
        __syncthreads();
        const uint32_t sK = smbase + (t & 1) * 49152;
        const uint32_t sV = sK + 32768;

        qk_half(A,  sK, 0u,      qh, ql, lanoff);   // keys 0-63
        qk_half(Bs, sK, 16384u,  qh, ql, lanoff);   // keys 64-127
        softmax_pv(A,  sV, 0u,     lanoff);         // chain hides under B's QK
        softmax_pv(Bs, sV, 8192u,  lanoff);         // chain hides under A's PV
        __syncthreads();
    }

    // --- merge streams A and B (same lanes, no smem needed) ---
    {
        const float mf0 = fmaxf(A.mu0, Bs.mu0), mf1 = fmaxf(A.mu1, Bs.mu1);
        const float aA0 = ex2f(A.mu0 - mf0), aB0 = ex2f(Bs.mu0 - mf0);
        const float aA1 = ex2f(A.mu1 - mf1), aB1 = ex2f(Bs.mu1 - mf1);
        #pragma unroll
        for (int nb = 0; nb < 9; nb++) {
            A.o[nb][0] = A.o[nb][0] * aA0 + Bs.o[nb][0] * aB0;
            A.o[nb][1] = A.o[nb][1] * aA0 + Bs.o[nb][1] * aB0;
            A.o[nb][2] = A.o[nb][2] * aA1 + Bs.o[nb][2] * aB1;
            A.o[nb][3] = A.o[nb][3] * aA1 + Bs.o[nb][3] * aB1;
        }
    }

    // --- epilogue: divide by rowsum, stage via smem for coalesced stores ---
    float* sm = (float*)smraw;  // stride-68 staging, conflict-free
    const float i0 = 1.f / A.o[8][0], i1 = 1.f / A.o[8][2];
    const int r0 = w * 16 + g;
    #pragma unroll
    for (int nb = 0; nb < 8; nb++) {
        const int c0 = nb * 8 + 2 * tq;
        sm[c0 * 68 + r0]           = A.o[nb][0] * i0;
        sm[(c0 + 1) * 68 + r0]     = A.o[nb][1] * i0;
        sm[c0 * 68 + r0 + 8]       = A.o[nb][2] * i1;
        sm[(c0 + 1) * 68 + r0 + 8] = A.o[nb][3] * i1;
    }
    __syncthreads();
    #pragma unroll
    for (int k = 0; k < 8; k++) {
        int idx = tid + k * 128;
        int c = idx >> 4, i4 = (idx & 15) << 2;
        *(float4*)&out[((size_t)b * 64 + c) * 4096 + qblk * 64 + i4] =
            *(float4*)&sm[c * 68 + i4];
    }
}

// ---------------------------------------------------------------------------
// QKV projection, z-split: blockIdx.z selects q/k/v (no serial m loop).
// Fragments staged in smem, coalesced uint4 global stores.
// ---------------------------------------------------------------------------
__global__ void __launch_bounds__(256, 1) qkv_kernel(
    const float* __restrict__ x,
    const float* __restrict__ Wq, const float* __restrict__ bq,
    const float* __restrict__ Wk, const float* __restrict__ bk,
    const float* __restrict__ Wv, const float* __restrict__ bv)
{
    __shared__ float xs[4096];
    __shared__ __align__(16) float wstage[4096];
    __shared__ float bs[64];

    const int t  = threadIdx.x;
    const int b  = blockIdx.y;
    const int n0 = blockIdx.x * 64;
    const int m  = blockIdx.z;

    const float* Wm = (m == 0) ? Wq : (m == 1) ? Wk : Wv;
    const float* bm = (m == 0) ? bq : (m == 1) ? bk : bv;

    #pragma unroll
    for (int k = 0; k < 4; k++) {
        int e = t + k * 256;
        int c = e >> 4, tn4 = (e & 15) << 2;
        *(float4*)&xs[c * 64 + tn4] = *(const float4*)&x[(b * C_ + c) * N_ + n0 + tn4];
    }
    #pragma unroll
    for (int k = 0; k < 4; k++) {
        int e = (t + k * 256) * 4;
        *(float4*)&wstage[e] = *(const float4*)&Wm[e];
    }
    if (t < C_) bs[t] = bm[t];
    __syncthreads();

    const int tng = t & 15, og = t >> 4;
    const int tn0 = tng * 4, o0 = og * 4;

    float acc[4][4];
    #pragma unroll
    for (int oo = 0; oo < 4; oo++) {
        float bb = bs[o0 + oo];
        #pragma unroll
        for (int tt = 0; tt < 4; tt++) acc[oo][tt] = bb;
    }
    #pragma unroll 4
    for (int c = 0; c < C_; c++) {
        float xv[4];
        *(float4*)xv = *(float4*)&xs[c * 64 + tn0];
        #pragma unroll
        for (int oo = 0; oo < 4; oo++) {
            float w = wstage[(o0 + oo) * C_ + c];
            #pragma unroll
            for (int tt = 0; tt < 4; tt++) acc[oo][tt] += w * xv[tt];
        }
    }
    if (m == 0) {
        #pragma unroll
        for (int oo = 0; oo < 4; oo++)
            #pragma unroll
            for (int tt = 0; tt < 4; tt++) acc[oo][tt] *= LOG2E;
    }
    __syncthreads();   // all W reads done; wstage becomes frag staging

    uint32_t* stage = (uint32_t*)wstage;
    if (m < 2) {
        #pragma unroll
        for (int tt = 0; tt < 4; tt++) {
            int n = n0 + tn0 + tt;
            #pragma unroll
            for (int op = 0; op < 2; op++) {
                int c = o0 + 2 * op;
                float x0 = acc[2*op][tt], x1 = acc[2*op+1][tt];
                __half h0 = __float2half_rn(x0), h1 = __float2half_rn(x1);
                uint32_t hi_w = ((uint32_t)__half_as_ushort(h1) << 16)
                              | __half_as_ushort(h0);
                uint32_t lo_w = pkh(x0 - __half2float(h0), x1 - __half2float(h1));
                int loff, plane;
                if (m == 0) {
                    int rbl = (n >> 4) & 3, r = n & 15, gg = r & 7, hb = (r >> 3) & 1;
                    int cs = c >> 4, cc = c & 15;
                    int lane_ = gg * 4 + ((cc & 7) >> 1);
                    int idx = hb + ((cc >> 3) << 1);
                    loff = (((rbl * 2) * 4 + cs) * 32 + lane_) * 4 + idx;
                    plane = 512;
                } else {
                    int jj = n & 63;
                    int cs = c >> 4, nb = jj >> 3, jp = nb >> 1, bsel = nb & 1;
                    int lane_ = (jj & 7) * 4 + ((c & 7) >> 1);
                    int idx = bsel * 2 + ((c & 15) >> 3);
                    loff = ((cs * 4 + jp) * 32 + lane_) * 4 + idx;
                    plane = 2048;
                }
                stage[loff] = hi_w;
                stage[loff + plane] = lo_w;
            }
        }
    } else {
        #pragma unroll
        for (int oo = 0; oo < 4; oo++) {
            int c = o0 + oo;
            #pragma unroll
            for (int tp = 0; tp < 2; tp++) {
                int jj = tn0 + 2 * tp;
                uint32_t hi_w = pkh(acc[oo][2*tp], acc[oo][2*tp+1]);
                int ks = jj >> 4, cp = c >> 4, bsel = (c >> 3) & 1;
                int lane_ = (c & 7) * 4 + ((jj & 7) >> 1);
                int idx = bsel * 2 + ((jj & 15) >> 3);
                stage[((ks * 4 + cp) * 32 + lane_) * 4 + idx] = hi_w;
            }
        }
    }
    __syncthreads();

    const uint4* src = (const uint4*)wstage;
    if (m == 0) {
        uint4* gd = g_qf + ((size_t)b * 256 + (n0 >> 4)) * 256;
        #pragma unroll
        for (int k = 0; k < 4; k++) { int i = t + k * 256; gd[i] = src[i]; }
    } else if (m == 1) {
        uint4* gd = g_kf + ((size_t)b * 64 + (n0 >> 6)) * 1024;
        #pragma unroll
        for (int k = 0; k < 4; k++) { int i = t + k * 256; gd[i] = src[i]; }
    } else {
        uint4* gd = g_vf + ((size_t)b * 64 + (n0 >> 6)) * 512;
        #pragma unroll
        for (int k = 0; k < 2; k++) { int i = t + k * 256; gd[i] = src[i]; }
    }
}

// ---------------------------------------------------------------------------
// Inputs (metadata order): x, t(unused), Wq, bq, Wk, bk, Wv, bv
// ---------------------------------------------------------------------------
extern "C" void kernel_launch(void* const* d_in, const int* in_sizes, int n_in,
                              void* d_out, int out_size) {
    const float* x  = (const float*)d_in[0];
    const float* Wq = (const float*)d_in[2];
    const float* bq = (const float*)d_in[3];
    const float* Wk = (const float*)d_in[4];
    const float* bk = (const float*)d_in[5];
    const float* Wv = (const float*)d_in[6];
    const float* bv = (const float*)d_in[7];
    float* out = (float*)d_out;

    cudaFuncSetAttribute(attn_tc, cudaFuncAttributeMaxDynamicSharedMemorySize,
                         98304);
    qkv_kernel<<<dim3(N_ / 64, B_, 3), 256>>>(x, Wq, bq, Wk, bk, Wv, bv);
    attn_tc<<<B_ * 64, 128, 98304>>>(out);
}

// round 10
// speedup vs baseline: 1.0508x; 1.0508x over previous
#include <cuda_runtime.h>
#include <cuda_fp16.h>
#include <cstdint>

#define B_ 4
#define C_ 64
#define N_ 4096
#define NT2 32              // 4096 / 128-key tiles
#define LOG2E 1.4426950408889634f
#define ONES16 0x3C003C00u
#define MLAG 3.5f           // lagging-max rescale threshold (log2 units)

// Fragment-ordered scratch. uint4 units.
__device__ uint4 g_qf[4 * 256 * 2 * 4 * 32];
__device__ uint4 g_kf[4 * 64 * 2 * 4 * 4 * 32];
__device__ uint4 g_vf[4 * 64 * 4 * 4 * 32];

// ---------------------------------------------------------------------------
__device__ __forceinline__ void cp16(uint32_t d, const void* g) {
    asm volatile("cp.async.cg.shared.global [%0], [%1], 16;"
                 :: "r"(d), "l"(__cvta_generic_to_global(g)) : "memory");
}
__device__ __forceinline__ uint4 lds128(uint32_t a) {
    uint4 r;
    asm volatile("ld.shared.v4.u32 {%0,%1,%2,%3}, [%4];"
                 : "=r"(r.x), "=r"(r.y), "=r"(r.z), "=r"(r.w) : "r"(a));
    return r;
}
__device__ __forceinline__ void mma16816(float* d, const uint32_t* a,
                                         uint32_t b0, uint32_t b1) {
    asm volatile("mma.sync.aligned.m16n8k16.row.col.f32.f16.f16.f32 "
        "{%0,%1,%2,%3}, {%4,%5,%6,%7}, {%8,%9}, {%0,%1,%2,%3};"
        : "+f"(d[0]), "+f"(d[1]), "+f"(d[2]), "+f"(d[3])
        : "r"(a[0]), "r"(a[1]), "r"(a[2]), "r"(a[3]), "r"(b0), "r"(b1));
}
__device__ __forceinline__ uint32_t cvtpk(float hi, float lo) {
    uint32_t r;
    asm("cvt.rn.f16x2.f32 %0, %1, %2;" : "=r"(r) : "f"(hi), "f"(lo));
    return r;
}
__device__ __forceinline__ uint32_t ex2x2(uint32_t a) {
    uint32_t r;
    asm("ex2.approx.f16x2 %0, %1;" : "=r"(r) : "r"(a));
    return r;
}
__device__ __forceinline__ float ex2f(float x) {
    float r;
    asm("ex2.approx.f32 %0, %1;" : "=f"(r) : "f"(x));
    return r;
}
__device__ __forceinline__ uint32_t pkh(float x0, float x1) {
    __half h0 = __float2half_rn(x0), h1 = __float2half_rn(x1);
    return ((uint32_t)__half_as_ushort(h1) << 16) | __half_as_ushort(h0);
}

// 128-key tile: K(hi+lo) 32KB + V(hi) 16KB. 128 threads.
__device__ __forceinline__ void copy_tile(uint32_t sdst, int b, int t2, int tid) {
    const uint4* gk = g_kf + ((size_t)b * 64 + t2 * 2) * 1024;
    const uint4* gv = g_vf + ((size_t)b * 64 + t2 * 2) * 512;
    #pragma unroll
    for (int k = 0; k < 16; k++) {
        int i = tid + k * 128;
        cp16(sdst + i * 16, gk + i);
    }
    #pragma unroll
    for (int k = 0; k < 8; k++) {
        int i = tid + k * 128;
        cp16(sdst + 32768 + i * 16, gv + i);
    }
}

// ---------------------------------------------------------------------------
// Flash attention: 64 q-rows/CTA (4 warps x 16 rows, full keys per warp),
// 128-key tiles. Deferred-PV + SPLIT softmax:
//   phase1 (reads s): fmax/shfl/cvtpk -> p_raw   [issued before next QK]
//   phase2 (s-free):  ex2(p), rare rescale, PV   [issued after next QK,
//                     retires under its queued MMAs]
// Lagging max: subtractor mu moves only when tile max exceeds mu+MLAG.
// ---------------------------------------------------------------------------
__global__ void __launch_bounds__(128, 2) attn_tc(float* __restrict__ out)
{
    extern __shared__ uint8_t smraw[];
    const uint32_t smbase = (uint32_t)__cvta_generic_to_shared(smraw);
    const int tid = threadIdx.x, w = tid >> 5, lane = tid & 31;
    const int g = lane >> 2, tq = lane & 3;
    const int b = blockIdx.x >> 6, qblk = blockIdx.x & 63;

    // persistent Q fragments (hi/lo), 32 regs
    uint32_t qh[4][4], ql[4][4];
    {
        const uint4* qp = g_qf + ((size_t)(b * 256 + qblk * 4 + w)) * 256 + lane;
        #pragma unroll
        for (int cs = 0; cs < 4; cs++) {
            uint4 h = qp[cs * 32];
            qh[cs][0] = h.x; qh[cs][1] = h.y; qh[cs][2] = h.z; qh[cs][3] = h.w;
            uint4 l = qp[128 + cs * 32];
            ql[cs][0] = l.x; ql[cs][1] = l.y; ql[cs][2] = l.z; ql[cs][3] = l.w;
        }
    }

    float o[9][4];
    #pragma unroll
    for (int nb = 0; nb < 9; nb++)
        #pragma unroll
        for (int i = 0; i < 4; i++) o[nb][i] = 0.f;
    float mu0 = -1e30f, mu1 = -1e30f;
    uint32_t p[16][2];            // raw (pre-ex2) then exp'd, previous tile
    float ra0 = 1.f, ra1 = 1.f;   // pending o-rescale factors
    int pend = 0;

    const uint32_t lanoff = (uint32_t)(lane * 16);
    float s[16][4];

    copy_tile(smbase, b, 0, tid);
    asm volatile("cp.async.commit_group;" ::: "memory");
    asm volatile("cp.async.wait_group 0;" ::: "memory");
    __syncthreads();
    copy_tile(smbase + 49152, b, 1, tid);
    asm volatile("cp.async.commit_group;" ::: "memory");

    // ---- macro-ish lambdas ----
    auto qk_tile = [&](uint32_t sK) {
        #pragma unroll
        for (int nb = 0; nb < 16; nb++)
            #pragma unroll
            for (int i = 0; i < 4; i++) s[nb][i] = 0.f;
        #pragma unroll
        for (int cs = 0; cs < 4; cs++) {
            #pragma unroll
            for (int jp = 0; jp < 8; jp++) {
                uint32_t base = sK + (jp >> 2) * 16384
                              + (cs * 4 + (jp & 3)) * 512 + lanoff;
                uint4 KH = lds128(base);
                uint4 KL = lds128(base + 8192);
                mma16816(s[2*jp],   qh[cs], KH.x, KH.y);
                mma16816(s[2*jp],   ql[cs], KH.x, KH.y);
                mma16816(s[2*jp],   qh[cs], KL.x, KL.y);
                mma16816(s[2*jp+1], qh[cs], KH.z, KH.w);
                mma16816(s[2*jp+1], ql[cs], KH.z, KH.w);
                mma16816(s[2*jp+1], qh[cs], KL.z, KL.w);
            }
        }
    };

    auto phase1 = [&]() {   // reads s: tile max, maybe move mu, cvtpk -> p raw
        float t0 = fmaxf(fmaxf(s[0][0], s[0][1]), fmaxf(s[1][0], s[1][1]));
        float t1 = fmaxf(fmaxf(s[0][2], s[0][3]), fmaxf(s[1][2], s[1][3]));
        #pragma unroll
        for (int nb = 2; nb < 16; nb += 2) {
            t0 = fmaxf(t0, fmaxf(fmaxf(s[nb][0], s[nb][1]),
                                 fmaxf(s[nb+1][0], s[nb+1][1])));
            t1 = fmaxf(t1, fmaxf(fmaxf(s[nb][2], s[nb][3]),
                                 fmaxf(s[nb+1][2], s[nb+1][3])));
        }
        t0 = fmaxf(t0, __shfl_xor_sync(0xffffffffu, t0, 1));
        t0 = fmaxf(t0, __shfl_xor_sync(0xffffffffu, t0, 2));
        t1 = fmaxf(t1, __shfl_xor_sync(0xffffffffu, t1, 1));
        t1 = fmaxf(t1, __shfl_xor_sync(0xffffffffu, t1, 2));
        bool need = (t0 > mu0 + MLAG) || (t1 > mu1 + MLAG);
        if (__ballot_sync(0xffffffffu, need)) {
            const float m0n = fmaxf(mu0, t0), m1n = fmaxf(mu1, t1);
            ra0 = ex2f(mu0 - m0n); ra1 = ex2f(mu1 - m1n);
            mu0 = m0n; mu1 = m1n; pend = 1;
        }
        #pragma unroll
        for (int nb = 0; nb < 16; nb++) {
            p[nb][0] = cvtpk(s[nb][1] - mu0, s[nb][0] - mu0);
            p[nb][1] = cvtpk(s[nb][3] - mu1, s[nb][2] - mu1);
        }
    };

    auto phase2_pv = [&](uint32_t sVp) {  // s-free: ex2, rescale, PV
        #pragma unroll
        for (int nb = 0; nb < 16; nb++) {
            p[nb][0] = ex2x2(p[nb][0]);
            p[nb][1] = ex2x2(p[nb][1]);
        }
        if (pend) {
            #pragma unroll
            for (int nb = 0; nb < 9; nb++) {
                o[nb][0] *= ra0; o[nb][1] *= ra0;
                o[nb][2] *= ra1; o[nb][3] *= ra1;
            }
            pend = 0;
        }
        #pragma unroll
        for (int s4 = 0; s4 < 8; s4++) {
            uint32_t a[4] = { p[2*s4][0], p[2*s4][1],
                              p[2*s4+1][0], p[2*s4+1][1] };
            #pragma unroll
            for (int cp = 0; cp < 4; cp++) {
                uint4 VH = lds128(sVp + (s4 >> 2) * 8192
                                  + ((s4 & 3) * 4 + cp) * 512 + lanoff);
                mma16816(o[2*cp],   a, VH.x, VH.y);
                mma16816(o[2*cp+1], a, VH.z, VH.w);
            }
            mma16816(o[8], a, ONES16, ONES16);
        }
    };

    // ---- tile 0: QK + phase1 only ----
    qk_tile(smbase);
    phase1();

    // ---- main loop ----
    for (int t = 1; t < NT2; t++) {
        asm volatile("cp.async.wait_group 0;" ::: "memory");
        __syncthreads();
        const uint32_t sK  = smbase + (t & 1) * 49152;                 // tile t
        const uint32_t sVp = smbase + ((t + 1) & 1) * 49152 + 32768;   // V(t-1)

        qk_tile(sK);          // 192 MMAs queued; phase2 drains beneath them
        phase2_pv(sVp);       // ex2 + rare rescale + 72 PV MMAs

        __syncthreads();      // all V(t-1) reads done
        if (t + 1 < NT2) {
            copy_tile(smbase + ((t + 1) & 1) * 49152, b, t + 1, tid);
            asm volatile("cp.async.commit_group;" ::: "memory");
        }
        phase1();             // reads s(t) before QK(t+1) rewrites it
    }

    // ---- tail: PV(NT2-1) ----
    phase2_pv(smbase + ((NT2 - 1) & 1) * 49152 + 32768);
    __syncthreads();

    // --- epilogue: divide by rowsum, stage via smem for coalesced stores ---
    float* sm = (float*)smraw;  // stride-68 staging, conflict-free
    const float i0 = 1.f / o[8][0], i1 = 1.f / o[8][2];
    const int r0 = w * 16 + g;
    #pragma unroll
    for (int nb = 0; nb < 8; nb++) {
        const int c0 = nb * 8 + 2 * tq;
        sm[c0 * 68 + r0]           = o[nb][0] * i0;
        sm[(c0 + 1) * 68 + r0]     = o[nb][1] * i0;
        sm[c0 * 68 + r0 + 8]       = o[nb][2] * i1;
        sm[(c0 + 1) * 68 + r0 + 8] = o[nb][3] * i1;
    }
    __syncthreads();
    #pragma unroll
    for (int k = 0; k < 8; k++) {
        int idx = tid + k * 128;
        int c = idx >> 4, i4 = (idx & 15) << 2;
        *(float4*)&out[((size_t)b * 64 + c) * 4096 + qblk * 64 + i4] =
            *(float4*)&sm[c * 68 + i4];
    }
}

// ---------------------------------------------------------------------------
// QKV projection, z-split: blockIdx.z selects q/k/v. (unchanged from R9)
// ---------------------------------------------------------------------------
__global__ void __launch_bounds__(256, 1) qkv_kernel(
    const float* __restrict__ x,
    const float* __restrict__ Wq, const float* __restrict__ bq,
    const float* __restrict__ Wk, const float* __restrict__ bk,
    const float* __restrict__ Wv, const float* __restrict__ bv)
{
    __shared__ float xs[4096];
    __shared__ __align__(16) float wstage[4096];
    __shared__ float bs[64];

    const int t  = threadIdx.x;
    const int b  = blockIdx.y;
    const int n0 = blockIdx.x * 64;
    const int m  = blockIdx.z;

    const float* Wm = (m == 0) ? Wq : (m == 1) ? Wk : Wv;
    const float* bm = (m == 0) ? bq : (m == 1) ? bk : bv;

    #pragma unroll
    for (int k = 0; k < 4; k++) {
        int e = t + k * 256;
        int c = e >> 4, tn4 = (e & 15) << 2;
        *(float4*)&xs[c * 64 + tn4] = *(const float4*)&x[(b * C_ + c) * N_ + n0 + tn4];
    }
    #pragma unroll
    for (int k = 0; k < 4; k++) {
        int e = (t + k * 256) * 4;
        *(float4*)&wstage[e] = *(const float4*)&Wm[e];
    }
    if (t < C_) bs[t] = bm[t];
    __syncthreads();

    const int tng = t & 15, og = t >> 4;
    const int tn0 = tng * 4, o0 = og * 4;

    float acc[4][4];
    #pragma unroll
    for (int oo = 0; oo < 4; oo++) {
        float bb = bs[o0 + oo];
        #pragma unroll
        for (int tt = 0; tt < 4; tt++) acc[oo][tt] = bb;
    }
    #pragma unroll 4
    for (int c = 0; c < C_; c++) {
        float xv[4];
        *(float4*)xv = *(float4*)&xs[c * 64 + tn0];
        #pragma unroll
        for (int oo = 0; oo < 4; oo++) {
            float w = wstage[(o0 + oo) * C_ + c];
            #pragma unroll
            for (int tt = 0; tt < 4; tt++) acc[oo][tt] += w * xv[tt];
        }
    }
    if (m == 0) {
        #pragma unroll
        for (int oo = 0; oo < 4; oo++)
            #pragma unroll
            for (int tt = 0; tt < 4; tt++) acc[oo][tt] *= LOG2E;
    }
    __syncthreads();   // all W reads done; wstage becomes frag staging

    uint32_t* stage = (uint32_t*)wstage;
    if (m < 2) {
        #pragma unroll
        for (int tt = 0; tt < 4; tt++) {
            int n = n0 + tn0 + tt;
            #pragma unroll
            for (int op = 0; op < 2; op++) {
                int c = o0 + 2 * op;
                float x0 = acc[2*op][tt], x1 = acc[2*op+1][tt];
                __half h0 = __float2half_rn(x0), h1 = __float2half_rn(x1);
                uint32_t hi_w = ((uint32_t)__half_as_ushort(h1) << 16)
                              | __half_as_ushort(h0);
                uint32_t lo_w = pkh(x0 - __half2float(h0), x1 - __half2float(h1));
                int loff, plane;
                if (m == 0) {
                    int rbl = (n >> 4) & 3, r = n & 15, gg = r & 7, hb = (r >> 3) & 1;
                    int cs = c >> 4, cc = c & 15;
                    int lane_ = gg * 4 + ((cc & 7) >> 1);
                    int idx = hb + ((cc >> 3) << 1);
                    loff = (((rbl * 2) * 4 + cs) * 32 + lane_) * 4 + idx;
                    plane = 512;
                } else {
                    int jj = n & 63;
                    int cs = c >> 4, nb = jj >> 3, jp = nb >> 1, bsel = nb & 1;
                    int lane_ = (jj & 7) * 4 + ((c & 7) >> 1);
                    int idx = bsel * 2 + ((c & 15) >> 3);
                    loff = ((cs * 4 + jp) * 32 + lane_) * 4 + idx;
                    plane = 2048;
                }
                stage[loff] = hi_w;
                stage[loff + plane] = lo_w;
            }
        }
    } else {
        #pragma unroll
        for (int oo = 0; oo < 4; oo++) {
            int c = o0 + oo;
            #pragma unroll
            for (int tp = 0; tp < 2; tp++) {
                int jj = tn0 + 2 * tp;
                uint32_t hi_w = pkh(acc[oo][2*tp], acc[oo][2*tp+1]);
                int ks = jj >> 4, cp = c >> 4, bsel = (c >> 3) & 1;
                int lane_ = (c & 7) * 4 + ((jj & 7) >> 1);
                int idx = bsel * 2 + ((jj & 15) >> 3);
                stage[((ks * 4 + cp) * 32 + lane_) * 4 + idx] = hi_w;
            }
        }
    }
    __syncthreads();

    const uint4* src = (const uint4*)wstage;
    if (m == 0) {
        uint4* gd = g_qf + ((size_t)b * 256 + (n0 >> 4)) * 256;
        #pragma unroll
        for (int k = 0; k < 4; k++) { int i = t + k * 256; gd[i] = src[i]; }
    } else if (m == 1) {
        uint4* gd = g_kf + ((size_t)b * 64 + (n0 >> 6)) * 1024;
        #pragma unroll
        for (int k = 0; k < 4; k++) { int i = t + k * 256; gd[i] = src[i]; }
    } else {
        uint4* gd = g_vf + ((size_t)b * 64 + (n0 >> 6)) * 512;
        #pragma unroll
        for (int k = 0; k < 2; k++) { int i = t + k * 256; gd[i] = src[i]; }
    }
}

// ---------------------------------------------------------------------------
// Inputs (metadata order): x, t(unused), Wq, bq, Wk, bk, Wv, bv
// ---------------------------------------------------------------------------
extern "C" void kernel_launch(void* const* d_in, const int* in_sizes, int n_in,
                              void* d_out, int out_size) {
    const float* x  = (const float*)d_in[0];
    const float* Wq = (const float*)d_in[2];
    const float* bq = (const float*)d_in[3];
    const float* Wk = (const float*)d_in[4];
    const float* bk = (const float*)d_in[5];
    const float* Wv = (const float*)d_in[6];
    const float* bv = (const float*)d_in[7];
    float* out = (float*)d_out;

    cudaFuncSetAttribute(attn_tc, cudaFuncAttributeMaxDynamicSharedMemorySize,
                         98304);
    qkv_kernel<<<dim3(N_ / 64, B_, 3), 256>>>(x, Wq, bq, Wk, bk, Wv, bv);
    attn_tc<<<B_ * 64, 128, 98304>>>(out);
}